// round 14
// baseline (speedup 1.0000x reference)
#include <cuda_runtime.h>

// out[t][l][d]: l==0 -> inputs[t][d], else memory[l][d]
// T=2048, L=64, D=1024 fp32. Pure store-bandwidth kernel (512 MiB compulsory
// writes). FINAL champion configuration (R10):
//   - block = 256 threads = one float4-row of D; U=2 rows per block, batched
//     loads then batched stores (best point of the U-sweep: 8/4/2/1 ->
//     75.0/74.2/73.9/74.5 us; interleaved 74.6; 512-thr 74.6)
//   - __ldg loads (input rows DRAM-once; 258 KiB tail L2-resident)
//   - __stcs evict-first streaming stores (A/B vs write-back: 73.9 vs 82.7)
// Achieves ~7.4 TB/s effective = ~92% of HBM3e spec; all SM pipes <10% busy
// -> verified DRAM write-drain roofline.

static constexpr int T = 2048;
static constexpr int L = 64;
static constexpr int D4 = 1024 / 4;            // 256 float4 per row
static constexpr int ROWS = T * L;             // 131072
static constexpr int U = 2;                    // rows per block

__global__ __launch_bounds__(256, 8)
void sliding_window_memory_kernel(const float4* __restrict__ in,
                                  const float4* __restrict__ mem,
                                  float4* __restrict__ out)
{
    const int tid = threadIdx.x;
    const int row0 = blockIdx.x * U;

    float4* __restrict__ o = out + (long)row0 * D4 + tid;

    float4 v[U];
#pragma unroll
    for (int u = 0; u < U; ++u) {
        const int row = row0 + u;
        const int l = row & (L - 1);
        const int t = row >> 6;
        const float4* __restrict__ s =
            (l == 0) ? (in + t * D4 + tid) : (mem + l * D4 + tid);
        v[u] = __ldg(s);                  // in: DRAM once; mem tail: L2-resident
    }
#pragma unroll
    for (int u = 0; u < U; ++u) {
        __stcs(o + u * D4, v[u]);         // streaming store
    }
}

extern "C" void kernel_launch(void* const* d_in, const int* in_sizes, int n_in,
                              void* d_out, int out_size)
{
    const float4* in  = (const float4*)d_in[0];   // inputs [T, D] fp32
    const float4* mem = (const float4*)d_in[1];   // memory [L, D] fp32
    float4* out = (float4*)d_out;                 // [T, L, D] fp32

    const int threads = 256;
    const int blocks = ROWS / U;                  // 65536
    sliding_window_memory_kernel<<<blocks, threads>>>(in, mem, out);
}